// round 16
// baseline (speedup 1.0000x reference)
#include <cuda_runtime.h>
#include <cstdint>

#define Bn 2048
#define Tn 512
#define Hn 16
#define Ln 8
#define CWPB 7                          // consumer warps per CTA (2 batches each)
#define BPC (CWPB * 2)                  // 14 batches per CTA
#define NBLK ((Bn + BPC - 1) / BPC)     // 147 CTAs -> 1 per SM
#define THREADS 256                     // 7 consumer warps + 1 producer warp (wid 7 -> SMSP 3)
#define CH 8                            // steps per chunk
#define NCH (Tn / CH)                   // 64 chunks

typedef unsigned long long ull;
typedef unsigned int u32;

// Ping-pong scratch for inter-layer hidden sequences (64 MB each).
__device__ float g_bufA[(size_t)Bn * Tn * Hn];
__device__ float g_bufB[(size_t)Bn * Tn * Hn];

// ---- packed fp32x2 ops (Blackwell) ----
__device__ __forceinline__ void ffma2(ull& d, ull a, ull b) {
    asm("fma.rn.f32x2 %0, %1, %2, %0;" : "+l"(d) : "l"(a), "l"(b));
}
__device__ __forceinline__ ull fmul2(ull a, ull b) {
    ull r; asm("mul.rn.f32x2 %0, %1, %2;" : "=l"(r) : "l"(a), "l"(b)); return r;
}
__device__ __forceinline__ float2 u2f(ull a) {
    float2 f;
    asm("mov.b64 {%0,%1}, %2;" : "=f"(f.x), "=f"(f.y) : "l"(a));
    return f;
}
__device__ __forceinline__ ull pack2(float x, float y) {
    ull r;
    asm("mov.b64 %0, {%1,%2};" : "=l"(r) : "f"(x), "f"(y));
    return r;
}
// Load 16 contiguous floats as 8 packed f32x2 (4x 128-bit loads).
__device__ __forceinline__ void load8(ull* d, const float* p) {
    const ulonglong2* q = (const ulonglong2*)p;
    ulonglong2 v0 = q[0], v1 = q[1], v2 = q[2], v3 = q[3];
    d[0] = v0.x; d[1] = v0.y; d[2] = v1.x; d[3] = v1.y;
    d[4] = v2.x; d[5] = v2.y; d[6] = v3.x; d[7] = v3.y;
}
__device__ __forceinline__ float tanha(float x) {
    float r; asm("tanh.approx.f32 %0, %1;" : "=f"(r) : "f"(x)); return r;
}
// Predicated GLOBAL store — single @p STG, no BSSY/BSYNC. Global addresses only.
__device__ __forceinline__ void st_pred(float* addr, float v, int pred) {
    asm volatile("{ .reg .pred p; setp.ne.s32 p, %0, 0; @p st.global.f32 [%1], %2; }"
                 :: "r"(pred), "l"(addr), "f"(v));
}
__device__ __forceinline__ void cp16(u32 saddr, const float* g) {
    asm volatile("cp.async.cg.shared.global [%0], [%1], 16;" :: "r"(saddr), "l"(g));
}
__device__ __forceinline__ void cp_commit() { asm volatile("cp.async.commit_group;"); }
__device__ __forceinline__ void cp_wait0()  { asm volatile("cp.async.wait_group 0;"); }
__device__ __forceinline__ void cp_wait1()  { asm volatile("cp.async.wait_group 1;"); }
// Arrival-count barrier: well-defined with warps arriving from divergent code.
__device__ __forceinline__ void barrier_all() {
    asm volatile("bar.sync 0, %0;" :: "r"(THREADS) : "memory");
}

// Warp-specialized LSTM layer.
//  Warps 0..6 (consumers): 2 batches each; lane (half,j) owns unit j of its batch.
//    Per step: h-projection (4 gates) + x-projection for gates i,f,o (pipelined),
//    g-gate x-projection read from the producer's smem plane.
//  Warp 7 (producer, SMSP 3 = idle capacity): g-gate x-projection for all 14
//    batches, one chunk ahead, via its own cp.async x staging.
template <bool WRITE_ALL>
__global__ void __launch_bounds__(THREADS, 1)
lstm_layer(const float* __restrict__ in, float* __restrict__ out,
           const float* __restrict__ Wih, const float* __restrict__ Whh,
           const float* __restrict__ bih, const float* __restrict__ bhh)
{
    __shared__ __align__(16) float sh[CWPB][2][2][Hn];            // h exchange
    __shared__ __align__(16) float xs[CWPB][2][2][CH][Hn];        // consumer x staging (28 KB)
    __shared__ __align__(16) float xg[2][CWPB][2][CH][Hn];        // g-gate xproj plane (14 KB)
    __shared__ __align__(16) float xps[2][CWPB][2][CH][Hn];       // producer x staging (14 KB)

    const int wid  = threadIdx.x >> 5;
    const int lane = threadIdx.x & 31;
    const int half = lane >> 4;
    const int j    = lane & 15;
    const bool isprod = (wid == CWPB);

    if (!isprod) {
        // ========================= CONSUMER =========================
        const int w = wid;
        int b = blockIdx.x * BPC + w * 2 + half;
        const int valid = (b < Bn);
        if (b >= Bn) b = 0;                       // clamp (reads safe, stores predicated)

        // weights: all 4 h rows; x rows for gates 0(i),1(f),3(o); sigmoid rows pre-halved.
        ull wh[4][8], wxA[3][8], bias[3];
        const ull halfpack = pack2(0.5f, 0.5f);
#pragma unroll
        for (int q = 0; q < 4; q++) {
            load8(wh[q], Whh + (q * Hn + j) * Hn);
            if (q != 2) {
#pragma unroll
                for (int i = 0; i < 8; i++) wh[q][i] = fmul2(wh[q][i], halfpack);
            }
        }
        const int xrows[3] = {0, 1, 3};
#pragma unroll
        for (int q = 0; q < 3; q++) {
            const int row = xrows[q] * Hn + j;
            load8(wxA[q], Wih + row * Hn);
#pragma unroll
            for (int i = 0; i < 8; i++) wxA[q][i] = fmul2(wxA[q][i], halfpack);
            bias[q] = pack2(0.5f * (bih[row] + bhh[row]), 0.0f);
        }

        sh[w][0][half][j] = 0.0f;
        float c = 0.0f;

        const float* xptr = in + (size_t)b * Tn * Hn;
        float*       orow = out + (size_t)b * Tn * Hn;

        // stage x chunk 0
        {
            u32 s0 = (u32)__cvta_generic_to_shared(&xs[w][0][half][0][0]);
            cp16(s0 + (j * 2) * 16,     xptr + j * 8);
            cp16(s0 + (j * 2 + 1) * 16, xptr + j * 8 + 4);
            cp_commit();
            cp_wait0();
        }
        __syncwarp();

        // initial x-projection (gates i,f,o) for step 0
        ull ax0, ax1, ax3;
        {
            ull xv[8];
            load8(xv, &xs[w][0][half][0][0]);
            ax0 = bias[0]; ax1 = bias[1]; ax3 = bias[2];
#pragma unroll
            for (int i = 0; i < 8; i++) {
                ffma2(ax0, wxA[0][i], xv[i]); ffma2(ax1, wxA[1][i], xv[i]);
                ffma2(ax3, wxA[2][i], xv[i]);
            }
        }

        barrier_all();   // producer has published xg chunk 0

        auto STEP = [&](int buf, int s, int t, const float* xsrc) {
            const float xgv = xg[buf][w][half][s][j];   // g-gate xproj (bias folded)
            ull hp[8];
            load8(hp, &sh[w][s & 1][half][0]);
            ull a0 = ax0, a1 = ax1, a3 = ax3;
            ull a2 = pack2(xgv, 0.0f);
#pragma unroll
            for (int i = 0; i < 8; i++) {
                ffma2(a0, wh[0][i], hp[i]); ffma2(a1, wh[1][i], hp[i]);
                ffma2(a2, wh[2][i], hp[i]); ffma2(a3, wh[3][i], hp[i]);
            }
            // pipelined x-projection (gates i,f,o) for the next step
            {
                ull xv[8];
                load8(xv, xsrc);
                ax0 = bias[0]; ax1 = bias[1]; ax3 = bias[2];
#pragma unroll
                for (int i = 0; i < 8; i++) {
                    ffma2(ax0, wxA[0][i], xv[i]); ffma2(ax1, wxA[1][i], xv[i]);
                    ffma2(ax3, wxA[2][i], xv[i]);
                }
            }
            float2 F0 = u2f(a0), F1 = u2f(a1), F2 = u2f(a2), F3 = u2f(a3);
            const float vi = F0.x + F0.y;   // pre-halved
            const float vf = F1.x + F1.y;   // pre-halved
            const float vg = F2.x + F2.y;
            const float vo = F3.x + F3.y;   // pre-halved

            const float si = fmaf(0.5f, tanha(vi), 0.5f);
            const float sf = fmaf(0.5f, tanha(vf), 0.5f);
            const float tg = tanha(vg);
            const float so = fmaf(0.5f, tanha(vo), 0.5f);

            c = fmaf(sf, c, si * tg);
            const float h = so * tanha(c);

            sh[w][(s + 1) & 1][half][j] = h;   // convergent STS->LDS handoff
            if (WRITE_ALL || t == Tn - 1)
                st_pred(orow + t * Hn + j, h, valid);
        };

        for (int ch = 0; ch < NCH; ch++) {
            const int cur = ch & 1;
            const int t0  = ch * CH;

            // stage x chunk ch+1 (clamped refetch at tail)
            {
                const int nch = (ch + 1 < NCH) ? ch + 1 : ch;
                const float* g = xptr + nch * (CH * Hn);
                u32 s0 = (u32)__cvta_generic_to_shared(&xs[w][cur ^ 1][half][0][0]);
                cp16(s0 + (j * 2) * 16,     g + j * 8);
                cp16(s0 + (j * 2 + 1) * 16, g + j * 8 + 4);
                cp_commit();
            }

#pragma unroll
            for (int s = 0; s < 4; s++)
                STEP(cur, s, t0 + s, &xs[w][cur][half][s + 1][0]);

            cp_wait0();          // chunk ch+1 resident (issued 4 steps ago)
            __syncwarp();

            STEP(cur, 4, t0 + 4, &xs[w][cur][half][5][0]);
            STEP(cur, 5, t0 + 5, &xs[w][cur][half][6][0]);
            STEP(cur, 6, t0 + 6, &xs[w][cur][half][7][0]);
            STEP(cur, 7, t0 + 7, &xs[w][cur ^ 1][half][0][0]);   // next chunk's step 0

            barrier_all();
        }
    } else {
        // ========================= PRODUCER (wid 7, SMSP 3) =========================
        // g-gate rows of Wih (row 32+j), no halving; bias folded.
        ull wxg[8];
        load8(wxg, Wih + (2 * Hn + j) * Hn);
        const ull biasg = pack2(bih[2 * Hn + j] + bhh[2 * Hn + j], 0.0f);

        const u32 xpsb[2] = {
            (u32)__cvta_generic_to_shared(&xps[0][0][0][0][0]),
            (u32)__cvta_generic_to_shared(&xps[1][0][0][0][0])
        };

        // stage x for chunk k into xps[k&1]: 448 16B segments, 14 per lane
        auto STAGE = [&](int k) {
#pragma unroll
            for (int i = 0; i < 14; i++) {
                const int idx = lane + 32 * i;          // 0..447
                const int cw  = idx >> 6;               // consumer warp
                const int hb  = (idx >> 5) & 1;         // batch half
                const int seg = idx & 31;               // 16B segment within (cw,hb)
                int bt = blockIdx.x * BPC + cw * 2 + hb;
                if (bt >= Bn) bt = 0;
                const float* g = in + (size_t)bt * Tn * Hn + k * (CH * Hn) + seg * 4;
                cp16(xpsb[k & 1] + (u32)idx * 16, g);
            }
            cp_commit();
        };

        // compute xg chunk k from xps[k&1]
        auto COMPUTE = [&](int k) {
            const int kb = k & 1;
            for (int cw = 0; cw < CWPB; cw++) {
#pragma unroll
                for (int s = 0; s < CH; s++) {
                    ull xv[8];
                    load8(xv, &xps[kb][cw][half][s][0]);
                    ull a = biasg;
#pragma unroll
                    for (int i = 0; i < 8; i++) ffma2(a, wxg[i], xv[i]);
                    float2 F = u2f(a);
                    xg[kb][cw][half][s][j] = F.x + F.y;
                }
            }
        };

        STAGE(0);
        STAGE(1);
        cp_wait1();          // chunk 0 resident
        __syncwarp();
        COMPUTE(0);
        __syncwarp();
        barrier_all();       // publish xg(0)

        for (int ch = 0; ch < NCH; ch++) {
            const int nk = (ch + 2 < NCH) ? ch + 2 : NCH - 1;
            STAGE(nk);                       // into xps[ch&1] (chunk ch done last iter)
            if (ch + 1 < NCH) {
                cp_wait1();                  // chunk ch+1 resident
                __syncwarp();
                COMPUTE(ch + 1);             // into xg[(ch+1)&1]
                __syncwarp();
            }
            barrier_all();
        }
    }
}

// Readout: position = last @ Wp^T + bp ; orientation = tanh(last @ Wo^T + bo)
__global__ void head_kernel(const float* __restrict__ hbuf,
                            const float* __restrict__ Wp, const float* __restrict__ bp,
                            const float* __restrict__ Wo, const float* __restrict__ bo,
                            float* __restrict__ out)
{
    int b = blockIdx.x * blockDim.x + threadIdx.x;
    if (b >= Bn) return;
    const float* h = hbuf + (size_t)b * Tn * Hn + (size_t)(Tn - 1) * Hn;
    float hv[16];
#pragma unroll
    for (int i = 0; i < 16; i++) hv[i] = h[i];

#pragma unroll
    for (int r = 0; r < 3; r++) {
        float s = bp[r];
#pragma unroll
        for (int k = 0; k < 16; k++) s += hv[k] * Wp[r * 16 + k];
        out[b * 6 + r] = s;
    }
#pragma unroll
    for (int r = 0; r < 3; r++) {
        float s = bo[r];
#pragma unroll
        for (int k = 0; k < 16; k++) s += hv[k] * Wo[r * 16 + k];
        out[b * 6 + 3 + r] = tanha(s);
    }
}

extern "C" void kernel_launch(void* const* d_in, const int* in_sizes, int n_in,
                              void* d_out, int out_size)
{
    const float* x   = (const float*)d_in[0];
    const float* Wih = (const float*)d_in[1];
    const float* Whh = (const float*)d_in[2];
    const float* bih = (const float*)d_in[3];
    const float* bhh = (const float*)d_in[4];
    const float* Wp  = (const float*)d_in[5];
    const float* bp  = (const float*)d_in[6];
    const float* Wo  = (const float*)d_in[7];
    const float* bo  = (const float*)d_in[8];
    float* out = (float*)d_out;

    float *bufA, *bufB;
    cudaGetSymbolAddress((void**)&bufA, g_bufA);
    cudaGetSymbolAddress((void**)&bufB, g_bufB);

    const float* cur = x;
    for (int l = 0; l < Ln; l++) {
        float* o = (l & 1) ? bufB : bufA;
        if (l != Ln - 1)
            lstm_layer<true><<<NBLK, THREADS>>>(cur, o,
                                                Wih + (size_t)l * 64 * Hn,
                                                Whh + (size_t)l * 64 * Hn,
                                                bih + (size_t)l * 64,
                                                bhh + (size_t)l * 64);
        else
            lstm_layer<false><<<NBLK, THREADS>>>(cur, o,
                                                 Wih + (size_t)l * 64 * Hn,
                                                 Whh + (size_t)l * 64 * Hn,
                                                 bih + (size_t)l * 64,
                                                 bhh + (size_t)l * 64);
        cur = o;
    }
    head_kernel<<<(Bn + 255) / 256, 256>>>(cur, Wp, bp, Wo, bo, out);
}

// round 17
// speedup vs baseline: 1.5044x; 1.5044x over previous
#include <cuda_runtime.h>
#include <cstdint>

#define Bn 2048
#define Tn 512
#define Hn 16
#define Ln 8
#define WPB 7                          // warps per CTA
#define BPC (WPB * 2)                  // 14 batches per CTA
#define NBLK ((Bn + BPC - 1) / BPC)    // 147 CTAs -> 1 per SM
#define CHUNK 16
#define NCHUNK (Tn / CHUNK)

typedef unsigned long long ull;
typedef unsigned int u32;

// Ping-pong scratch for inter-layer hidden sequences (64 MB each).
__device__ float g_bufA[(size_t)Bn * Tn * Hn];
__device__ float g_bufB[(size_t)Bn * Tn * Hn];

// ---- packed fp32x2 ops (Blackwell) ----
__device__ __forceinline__ void ffma2(ull& d, ull a, ull b) {
    asm("fma.rn.f32x2 %0, %1, %2, %0;" : "+l"(d) : "l"(a), "l"(b));
}
__device__ __forceinline__ ull fmul2(ull a, ull b) {
    ull r; asm("mul.rn.f32x2 %0, %1, %2;" : "=l"(r) : "l"(a), "l"(b)); return r;
}
__device__ __forceinline__ float2 u2f(ull a) {
    float2 f;
    asm("mov.b64 {%0,%1}, %2;" : "=f"(f.x), "=f"(f.y) : "l"(a));
    return f;
}
__device__ __forceinline__ ull pack2(float x, float y) {
    ull r;
    asm("mov.b64 %0, {%1,%2};" : "=l"(r) : "f"(x), "f"(y));
    return r;
}
// Load 16 contiguous floats as 8 packed f32x2 (4x 128-bit loads).
__device__ __forceinline__ void load8(ull* d, const float* p) {
    const ulonglong2* q = (const ulonglong2*)p;
    ulonglong2 v0 = q[0], v1 = q[1], v2 = q[2], v3 = q[3];
    d[0] = v0.x; d[1] = v0.y; d[2] = v1.x; d[3] = v1.y;
    d[4] = v2.x; d[5] = v2.y; d[6] = v3.x; d[7] = v3.y;
}
__device__ __forceinline__ float tanha(float x) {
    float r; asm("tanh.approx.f32 %0, %1;" : "=f"(r) : "f"(x)); return r;
}
__device__ __forceinline__ void cp16(u32 saddr, const float* g) {
    asm volatile("cp.async.cg.shared.global [%0], [%1], 16;" :: "r"(saddr), "l"(g));
}
__device__ __forceinline__ void cp_commit() { asm volatile("cp.async.commit_group;"); }
__device__ __forceinline__ void cp_wait0()  { asm volatile("cp.async.wait_group 0;"); }

// One LSTM layer. Warp = TWO batch elements (lanes 0-15 / 16-31).
// Lane (half, j) owns hidden unit j of its batch: gate rows j, 16+j, 32+j, 48+j.
// Weights in registers (f32x2; sigmoid rows pre-scaled by 0.5). h via a SINGLE
// smem slot (convergent LDS-before-STS within each step). x staged via cp.async
// chunks; x-projection pipelined one step ahead. Gate issue order follows the
// c-chain criticality: (i,f,g) first, o last.
template <bool WRITE_ALL>
__global__ void __launch_bounds__(224, 1)
lstm_layer(const float* __restrict__ in, float* __restrict__ out,
           const float* __restrict__ Wih, const float* __restrict__ Whh,
           const float* __restrict__ bih, const float* __restrict__ bhh)
{
    __shared__ __align__(16) float sh[WPB][2][Hn];               // [warp][half][j] (single buffer)
    __shared__ __align__(16) float xs[WPB][2][2][CHUNK][Hn];     // [warp][buf][half][step][j]

    const int warp = threadIdx.x >> 5;
    const int lane = threadIdx.x & 31;
    const int half = lane >> 4;
    const int j    = lane & 15;
    const int b    = blockIdx.x * BPC + warp * 2 + half;
    if (b >= Bn) return;   // warp-uniform exit

    // ---- weights -> registers; sigmoid-gate rows scaled by 0.5 ----
    ull wx[4][8], wh[4][8], bias[4];
    const ull halfpack = pack2(0.5f, 0.5f);
#pragma unroll
    for (int q = 0; q < 4; q++) {
        const int row = q * Hn + j;          // q: 0=i 1=f 2=g 3=o
        load8(wx[q], Wih + row * Hn);
        load8(wh[q], Whh + row * Hn);
        float bb = bih[row] + bhh[row];
        if (q != 2) {
            bb *= 0.5f;
#pragma unroll
            for (int i = 0; i < 8; i++) {
                wx[q][i] = fmul2(wx[q][i], halfpack);
                wh[q][i] = fmul2(wh[q][i], halfpack);
            }
        }
        bias[q] = pack2(bb, 0.0f);
    }

    sh[warp][half][j] = 0.0f;
    float c = 0.0f;

    const float* xptr = in + (size_t)b * Tn * Hn;
    float*       orow = out + (size_t)b * Tn * Hn;

    // prefetch chunk 0 into buf 0 and wait
    {
        u32 s0 = (u32)__cvta_generic_to_shared(&xs[warp][0][half][0][0]);
#pragma unroll
        for (int k = 0; k < 4; k++)
            cp16(s0 + (k * 16 + j) * 16, xptr + (k * 16 + j) * 4);
        cp_commit();
        cp_wait0();
    }
    __syncwarp();

    // initial x-projection: chunk 0, step 0
    ull ax0, ax1, ax2, ax3;
    {
        ull xv[8];
        load8(xv, &xs[warp][0][half][0][0]);
        ax0 = bias[0]; ax1 = bias[1]; ax2 = bias[2]; ax3 = bias[3];
#pragma unroll
        for (int i = 0; i < 8; i++) {
            ffma2(ax0, wx[0][i], xv[i]); ffma2(ax1, wx[1][i], xv[i]);
            ffma2(ax2, wx[2][i], xv[i]); ffma2(ax3, wx[3][i], xv[i]);
        }
    }

    // One LSTM step. Criticality order: h-proj for i,f,g first (c-chain), o last.
    auto STEP = [&](int t, const float* xsrc) {
        ull hp[8];
        load8(hp, &sh[warp][half][0]);           // LDS precedes this step's STS
        ull a0 = ax0, a1 = ax1, a2 = ax2, a3 = ax3;
#pragma unroll
        for (int i = 0; i < 8; i++) {            // c-chain gates: i, f, g
            ffma2(a0, wh[0][i], hp[i]);
            ffma2(a1, wh[1][i], hp[i]);
            ffma2(a2, wh[2][i], hp[i]);
        }
        // c-chain head: horizontals + MUFUs for i,f,g start ASAP
        float2 F0 = u2f(a0), F1 = u2f(a1), F2 = u2f(a2);
        const float vi = F0.x + F0.y;            // pre-halved
        const float vf = F1.x + F1.y;            // pre-halved
        const float vg = F2.x + F2.y;
        const float tg = tanha(vg);
        const float sf = fmaf(0.5f, tanha(vf), 0.5f);
        const float si = fmaf(0.5f, tanha(vi), 0.5f);

        // o gate h-proj (needed only at the very end)
#pragma unroll
        for (int i = 0; i < 8; i++)
            ffma2(a3, wh[3][i], hp[i]);

        // off-chain: next x-projection (fills the activation-latency window)
        {
            ull xv[8];
            load8(xv, xsrc);
            ax0 = bias[0]; ax1 = bias[1]; ax2 = bias[2]; ax3 = bias[3];
#pragma unroll
            for (int i = 0; i < 8; i++) {
                ffma2(ax0, wx[0][i], xv[i]); ffma2(ax1, wx[1][i], xv[i]);
                ffma2(ax2, wx[2][i], xv[i]); ffma2(ax3, wx[3][i], xv[i]);
            }
        }

        c = fmaf(sf, c, si * tg);
        const float thc = tanha(c);
        float2 F3 = u2f(a3);
        const float vo = F3.x + F3.y;            // pre-halved
        const float so = fmaf(0.5f, tanha(vo), 0.5f);
        const float h = so * thc;

        sh[warp][half][j] = h;                   // convergent STS after all LDS of this step
        if (WRITE_ALL || t == Tn - 1)            // warp-uniform condition
            orow[t * Hn + j] = h;
    };

    for (int ch = 0; ch < NCHUNK; ch++) {
        const int cur = ch & 1;
        const int t0  = ch * CHUNK;

        // issue prefetch of chunk ch+1 into buf cur^1 (clamped refetch at tail)
        {
            const int nch = (ch + 1 < NCHUNK) ? ch + 1 : ch;
            const float* g = xptr + nch * (CHUNK * Hn);
            u32 s0 = (u32)__cvta_generic_to_shared(&xs[warp][cur ^ 1][half][0][0]);
#pragma unroll
            for (int k = 0; k < 4; k++)
                cp16(s0 + (k * 16 + j) * 16, g + (k * 16 + j) * 4);
            cp_commit();
        }

#pragma unroll 4
        for (int s = 0; s < 12; s++)
            STEP(t0 + s, &xs[warp][cur][half][s + 1][0]);

        cp_wait0();          // chunk ch+1 resident (issued 12 steps ago)
        __syncwarp();        // cross-lane visibility of cp.async fills

        STEP(t0 + 12, &xs[warp][cur][half][13][0]);
        STEP(t0 + 13, &xs[warp][cur][half][14][0]);
        STEP(t0 + 14, &xs[warp][cur][half][15][0]);
        // s=15: refill ax from the NEXT chunk's slot 0 (already resident)
        STEP(t0 + 15, &xs[warp][cur ^ 1][half][0][0]);
    }
}

// Readout: position = last @ Wp^T + bp ; orientation = tanh(last @ Wo^T + bo)
__global__ void head_kernel(const float* __restrict__ hbuf,
                            const float* __restrict__ Wp, const float* __restrict__ bp,
                            const float* __restrict__ Wo, const float* __restrict__ bo,
                            float* __restrict__ out)
{
    int b = blockIdx.x * blockDim.x + threadIdx.x;
    if (b >= Bn) return;
    const float* h = hbuf + (size_t)b * Tn * Hn + (size_t)(Tn - 1) * Hn;
    float hv[16];
#pragma unroll
    for (int i = 0; i < 16; i++) hv[i] = h[i];

#pragma unroll
    for (int r = 0; r < 3; r++) {
        float s = bp[r];
#pragma unroll
        for (int k = 0; k < 16; k++) s += hv[k] * Wp[r * 16 + k];
        out[b * 6 + r] = s;
    }
#pragma unroll
    for (int r = 0; r < 3; r++) {
        float s = bo[r];
#pragma unroll
        for (int k = 0; k < 16; k++) s += hv[k] * Wo[r * 16 + k];
        out[b * 6 + 3 + r] = tanha(s);
    }
}

extern "C" void kernel_launch(void* const* d_in, const int* in_sizes, int n_in,
                              void* d_out, int out_size)
{
    const float* x   = (const float*)d_in[0];
    const float* Wih = (const float*)d_in[1];
    const float* Whh = (const float*)d_in[2];
    const float* bih = (const float*)d_in[3];
    const float* bhh = (const float*)d_in[4];
    const float* Wp  = (const float*)d_in[5];
    const float* bp  = (const float*)d_in[6];
    const float* Wo  = (const float*)d_in[7];
    const float* bo  = (const float*)d_in[8];
    float* out = (float*)d_out;

    float *bufA, *bufB;
    cudaGetSymbolAddress((void**)&bufA, g_bufA);
    cudaGetSymbolAddress((void**)&bufB, g_bufB);

    const float* cur = x;
    for (int l = 0; l < Ln; l++) {
        float* o = (l & 1) ? bufB : bufA;
        if (l != Ln - 1)
            lstm_layer<true><<<NBLK, 224>>>(cur, o,
                                            Wih + (size_t)l * 64 * Hn,
                                            Whh + (size_t)l * 64 * Hn,
                                            bih + (size_t)l * 64,
                                            bhh + (size_t)l * 64);
        else
            lstm_layer<false><<<NBLK, 224>>>(cur, o,
                                             Wih + (size_t)l * 64 * Hn,
                                             Whh + (size_t)l * 64 * Hn,
                                             bih + (size_t)l * 64,
                                             bhh + (size_t)l * 64);
        cur = o;
    }
    head_kernel<<<(Bn + 255) / 256, 256>>>(cur, Wp, bp, Wo, bo, out);
}